// round 6
// baseline (speedup 1.0000x reference)
#include <cuda_runtime.h>
#include <cuda_fp16.h>
#include <math.h>
#include <stdint.h>

// Problem constants
#define BSZ    256
#define HDIM   768
#define H3     2304
#define TSTEPS 128

// Tiling
#define JT       16               // j-columns per CTA (per gate)
#define NB       48               // 3 gates * JT rows of W per CTA
#define MTILE    128              // batch rows per CTA
#define KCHUNK   64               // K elems per A chunk (128B rows)
#define NCHUNKS  (HDIM / KCHUNK)  // 12
#define NSTAGES  4                // A pipeline depth
#define NTHREADS 512              // 16 warps
#define NJB      (HDIM / JT)      // 48
#define NCTA     96               // 48 x 2, all resident (1 CTA/SM)

// Dynamic SMEM layout (bytes)
//   W resident (single fp16): [chunk(12)][row(48)][128B], SW128  = 73728
//   A stages: 4 x (hi 16KB + lo 16KB) = 131072
#define WBYTES   (NCHUNKS * NB * 128)          // 73728
#define AOFF     WBYTES
#define APART    (MTILE * 128)                 // 16384
#define ABUF     (2 * APART)                   // 32768 per stage
#define SMEM_DYN (AOFF + NSTAGES * ABUF)       // 204800
#define CSTRIDE  49                            // fp32 C row stride in epilogue

// ---------------------------------------------------------------------------
// Device globals
// ---------------------------------------------------------------------------
__device__ __align__(16) __half g_hhi[2][BSZ * HDIM];  // fp16 hi of h
__device__ __align__(16) __half g_hlo[2][BSZ * HDIM];  // fp16 lo of h
__device__ __align__(16) __half g_wh[H3 * HDIM];       // fp16 W (single)
__device__ float    g_dotp[TSTEPS * NJB * BSZ];
__device__ unsigned g_bar;

// ---------------------------------------------------------------------------
// PTX helpers (baseline sm_80/90 features only — NO tcgen05)
// ---------------------------------------------------------------------------
__device__ __forceinline__ uint32_t smem_u32(const void* p) {
    uint32_t a;
    asm("{ .reg .u64 t; cvta.to.shared.u64 t, %1; cvt.u32.u64 %0, t; }"
        : "=r"(a) : "l"(p));
    return a;
}
__device__ __forceinline__ void cp16(uint32_t d, const void* s) {
    asm volatile("cp.async.cg.shared.global [%0], [%1], 16;" :: "r"(d), "l"(s));
}
__device__ __forceinline__ void cp_commit() {
    asm volatile("cp.async.commit_group;" ::: "memory");
}
template <int N>
__device__ __forceinline__ void cp_wait() {
    asm volatile("cp.async.wait_group %0;" :: "n"(N) : "memory");
}
__device__ __forceinline__ void ldsm_x4(uint32_t* r, uint32_t a) {
    asm volatile("ldmatrix.sync.aligned.m8n8.x4.shared.b16 {%0,%1,%2,%3}, [%4];"
                 : "=r"(r[0]), "=r"(r[1]), "=r"(r[2]), "=r"(r[3]) : "r"(a));
}
__device__ __forceinline__ void ldsm_x2(uint32_t* r, uint32_t a) {
    asm volatile("ldmatrix.sync.aligned.m8n8.x2.shared.b16 {%0,%1}, [%2];"
                 : "=r"(r[0]), "=r"(r[1]) : "r"(a));
}
__device__ __forceinline__ void mma_f16(float* c, const uint32_t* a, const uint32_t* b) {
    asm volatile(
        "mma.sync.aligned.m16n8k16.row.col.f32.f16.f16.f32 "
        "{%0,%1,%2,%3}, {%4,%5,%6,%7}, {%8,%9}, {%0,%1,%2,%3};"
        : "+f"(c[0]), "+f"(c[1]), "+f"(c[2]), "+f"(c[3])
        : "r"(a[0]), "r"(a[1]), "r"(a[2]), "r"(a[3]), "r"(b[0]), "r"(b[1]));
}
#define SW128(o) ((o) ^ (((o) >> 3) & 0x70))

// ---------------------------------------------------------------------------
// Prep kernels
// ---------------------------------------------------------------------------
__global__ void prep_w_kernel(const float* __restrict__ W) {
    int i = blockIdx.x * blockDim.x + threadIdx.x;
    if (i < H3 * HDIM) g_wh[i] = __float2half_rn(W[i]);
}
__global__ void prep_h_kernel(const float* __restrict__ ctx) {
    int i = blockIdx.x * blockDim.x + threadIdx.x;
    if (i == 0) g_bar = 0u;
    if (i < BSZ * HDIM) {
        float v = ctx[i];
        __half hi = __float2half_rn(v);
        g_hhi[0][i] = hi;
        g_hlo[0][i] = __float2half_rn(v - __half2float(hi));
    }
}

// ---------------------------------------------------------------------------
// Grid barrier (96 CTAs, 1/SM, all co-resident)
// ---------------------------------------------------------------------------
__device__ __forceinline__ void grid_barrier(unsigned target) {
    __syncthreads();
    if (threadIdx.x == 0) {
        __threadfence();
        atomicAdd(&g_bar, 1u);
        unsigned v;
        do { v = *(volatile unsigned*)&g_bar; } while (v < target);
        __threadfence();
    }
    __syncthreads();
}

// ---------------------------------------------------------------------------
// Persistent kernel: all 128 GRU steps.
// Grid (48, 2), 512 threads = 16 warps, warp tile 16x24.
// 2-term fp16: C = Ah*W + Al*W  (A = h split hi/lo, W rounded once)
// ---------------------------------------------------------------------------
__global__ __launch_bounds__(NTHREADS, 1) void persist_kernel(
    const float* __restrict__ context,
    const float* __restrict__ bias_ih,
    const float* __restrict__ bias_hh,
    const float* __restrict__ fc_w)
{
    extern __shared__ __align__(16) uint8_t smem[];
    __shared__ float sbr[JT], sbz[JT], sbni[JT], sbnh[JT], sfw[JT];

    const uint32_t sbase = smem_u32(smem);
    const int tid    = threadIdx.x;
    const int lane   = tid & 31;
    const int wid    = tid >> 5;
    const int warp_m = (wid & 7) * 16;     // 8 m-tiles of 16
    const int warp_n = (wid >> 3) * 24;    // 2 n-tiles of 24
    const int jb     = blockIdx.x;
    const int j0     = jb * JT;
    const int brow   = blockIdx.y * MTILE;

    // Epilogue ownership: thread = (batch row, j-quad)
    const int eb  = tid >> 2;              // 0..127
    const int ejq = (tid & 3) * 4;         // 0,4,8,12

    // ---- stage resident W (single fp16) into SMEM, SW128 swizzled ----
    for (int idx = tid; idx < NCHUNKS * NB * 8; idx += NTHREADS) {
        int ck  = idx / (NB * 8);
        int rem = idx - ck * (NB * 8);
        int r   = rem >> 3, cg = rem & 7;
        int wrow = (r >> 4) * HDIM + j0 + (r & 15);
        size_t so = (size_t)wrow * HDIM + ck * KCHUNK + cg * 8;
        uint32_t dst = (uint32_t)(ck * (NB * 128)) + SW128((uint32_t)(r * 128 + cg * 16));
        cp16(sbase + dst, g_wh + so);
    }
    cp_commit();   // W group

    if (tid < JT) {
        int j = j0 + tid;
        sbr[tid]  = bias_ih[j] + bias_hh[j];
        sbz[tid]  = bias_ih[HDIM + j] + bias_hh[HDIM + j];
        sbni[tid] = bias_ih[2 * HDIM + j];
        sbnh[tid] = bias_hh[2 * HDIM + j];
        sfw[tid]  = fc_w[j];
    }

    // fp32 h in registers: thread owns (brow+eb, j0+ejq..+3)
    float hreg[4];
    {
        const float* crow = context + (size_t)(brow + eb) * HDIM + j0 + ejq;
#pragma unroll
        for (int jj = 0; jj < 4; jj++) hreg[jj] = crow[jj];
    }
    __syncthreads();

    unsigned bar_target = 0;
    for (int t = 0; t < TSTEPS; t++) {
        const int rp = t & 1;
        const int wp = rp ^ 1;
        const __half* __restrict__ hhi = g_hhi[rp];
        const __half* __restrict__ hlo = g_hlo[rp];

        float acc[3][4];
#pragma unroll
        for (int ni = 0; ni < 3; ni++)
#pragma unroll
            for (int q = 0; q < 4; q++) acc[ni][q] = 0.0f;

        auto issueA = [&](int ck) {
            const int k0 = ck * KCHUNK;
            const uint32_t abase = sbase + AOFF + (uint32_t)(ck & (NSTAGES - 1)) * ABUF;
#pragma unroll
            for (int idx = tid; idx < MTILE * 8; idx += NTHREADS) {  // 2 iters
                int r = idx >> 3, cg = idx & 7;
                uint32_t off = SW128((uint32_t)(r * 128 + cg * 16));
                size_t so = (size_t)(brow + r) * HDIM + k0 + cg * 8;
                cp16(abase + off,         hhi + so);
                cp16(abase + APART + off, hlo + so);
            }
            cp_commit();
        };

        auto compute = [&](int ck) {
            const uint32_t abase = sbase + AOFF + (uint32_t)(ck & (NSTAGES - 1)) * ABUF;
            const uint32_t wbase = sbase + (uint32_t)(ck * (NB * 128));
#pragma unroll
            for (int ks = 0; ks < KCHUNK / 16; ks++) {
                const uint32_t kb = ks * 32;
                uint32_t ah[4], al[4], bw[3][2];
                {
                    uint32_t off = SW128(
                        (uint32_t)((warp_m + (lane & 15)) * 128) + kb +
                        ((lane >> 4) & 1) * 16);
                    ldsm_x4(ah, abase + off);
                    ldsm_x4(al, abase + APART + off);
                }
#pragma unroll
                for (int ni = 0; ni < 3; ni++) {
                    uint32_t off = SW128(
                        (uint32_t)((warp_n + ni * 8 + (lane & 7)) * 128) + kb +
                        ((lane >> 3) & 1) * 16);
                    ldsm_x2(bw[ni], wbase + off);
                }
#pragma unroll
                for (int ni = 0; ni < 3; ni++) {
                    mma_f16(acc[ni], ah, bw[ni]);
                    mma_f16(acc[ni], al, bw[ni]);
                }
            }
        };

        // ---- 4-stage pipeline, 1 sync per chunk ----
        issueA(0); issueA(1); issueA(2);
        for (int ck = 0; ck < NCHUNKS; ck++) {
            cp_wait<2>();          // chunk ck's group complete (this thread)
            __syncthreads();       // all threads' data visible
            if (ck + 3 < NCHUNKS) issueA(ck + 3);
            else                  cp_commit();   // empty group keeps count
            compute(ck);
        }

        // ---- C to SMEM (aliases A stage 0; last use was chunk 8, all
        //      threads are past the chunk-9+ syncs) ----
        float* Csm = (float*)(smem + AOFF);
        {
            const int r0 = lane >> 2, cpn = (lane & 3) * 2;
#pragma unroll
            for (int ni = 0; ni < 3; ni++) {
                int row = warp_m + r0;
                int col = warp_n + ni * 8 + cpn;
                Csm[row * CSTRIDE + col]           = acc[ni][0];
                Csm[row * CSTRIDE + col + 1]       = acc[ni][1];
                Csm[(row + 8) * CSTRIDE + col]     = acc[ni][2];
                Csm[(row + 8) * CSTRIDE + col + 1] = acc[ni][3];
            }
        }
        __syncthreads();

        // ---- gate epilogue: thread = (batch row, j-quad) ----
        {
            const int b = brow + eb;
            __half* __restrict__ hih = g_hhi[wp] + (size_t)b * HDIM + j0 + ejq;
            __half* __restrict__ hil = g_hlo[wp] + (size_t)b * HDIM + j0 + ejq;
            const float* crow = Csm + eb * CSTRIDE;

            float part = 0.0f;
#pragma unroll
            for (int q = 0; q < 4; q++) {
                const int jj = ejq + q;
                float rawr = crow[jj];
                float rawz = crow[JT + jj];
                float rawn = crow[2 * JT + jj];

                float rg = 1.0f / (1.0f + expf(-(sbr[jj] + rawr)));
                float zg = 1.0f / (1.0f + expf(-(sbz[jj] + rawz)));
                float ng = tanhf(sbni[jj] + rg * (rawn + sbnh[jj]));
                float hn = (1.0f - zg) * ng + zg * hreg[q];

                hreg[q] = hn;
                __half hi = __float2half_rn(hn);
                hih[q] = hi;
                hil[q] = __float2half_rn(hn - __half2float(hi));
                part += hn * sfw[jj];
            }
            part += __shfl_xor_sync(0xFFFFFFFFu, part, 1);
            part += __shfl_xor_sync(0xFFFFFFFFu, part, 2);
            if ((tid & 3) == 0)
                g_dotp[(size_t)t * NJB * BSZ + jb * BSZ + b] = part;
        }

        bar_target += NCTA;
        if (t + 1 < TSTEPS) grid_barrier(bar_target);   // also orders Csm reuse
        else                __syncthreads();
    }
}

// ---------------------------------------------------------------------------
// Finalize: dot = fixed-order sum of 48 partials, softplus, scan, normalize
// ---------------------------------------------------------------------------
__device__ __forceinline__ float softplusf_(float x) {
    return (x > 0.0f) ? (x + log1pf(expf(-x))) : log1pf(expf(x));
}

__global__ __launch_bounds__(TSTEPS) void finalize_kernel(
    const int* __restrict__ num_pred,
    const float* __restrict__ fc_b,
    float* __restrict__ out)
{
    __shared__ float s[TSTEPS];
    const int b = blockIdx.x;
    const int t = threadIdx.x;

    float dot = fc_b[0];
    const float* p = g_dotp + (size_t)t * NJB * BSZ + b;
#pragma unroll
    for (int jbk = 0; jbk < NJB; jbk++) dot += p[jbk * BSZ];
    s[t] = softplusf_(dot);
    __syncthreads();

#pragma unroll
    for (int off = 1; off < TSTEPS; off <<= 1) {
        float v = (t >= off) ? s[t - off] : 0.0f;
        __syncthreads();
        s[t] += v;
        __syncthreads();
    }

    const int n = num_pred[b];
    int idx = n - 1;
    if (idx < 0) idx = 0;
    if (idx > TSTEPS - 1) idx = TSTEPS - 1;
    const float last = s[idx] + 1e-6f;

    float* orow = out + (size_t)b * (TSTEPS + 2);
    float val;
    if (t < n)       val = s[t] / last;
    else if (t == n) val = 1.0f;
    else             val = 0.0f;
    orow[t + 1] = val;

    if (t == 0) {
        orow[0] = 0.0f;
        orow[TSTEPS + 1] = (n == TSTEPS) ? 1.0f : 0.0f;
    }
}

// ---------------------------------------------------------------------------
// Launch. Inputs: 0 context 1 weight_ih(unused) 2 weight_hh 3 bias_ih
//                 4 bias_hh 5 fc_w 6 fc_b 7 num_pred_list 8 max_steps
// ---------------------------------------------------------------------------
extern "C" void kernel_launch(void* const* d_in, const int* in_sizes, int n_in,
                              void* d_out, int out_size)
{
    const float* context  = (const float*)d_in[0];
    const float* Whh      = (const float*)d_in[2];
    const float* bias_ih  = (const float*)d_in[3];
    const float* bias_hh  = (const float*)d_in[4];
    const float* fc_w     = (const float*)d_in[5];
    const float* fc_b     = (const float*)d_in[6];
    const int*   num_pred = (const int*)d_in[7];
    float*       out      = (float*)d_out;

    static bool attr_set = false;
    if (!attr_set) {
        cudaFuncSetAttribute(persist_kernel,
                             cudaFuncAttributeMaxDynamicSharedMemorySize, SMEM_DYN);
        attr_set = true;
    }

    prep_w_kernel<<<(H3 * HDIM + 255) / 256, 256>>>(Whh);
    prep_h_kernel<<<(BSZ * HDIM + 255) / 256, 256>>>(context);

    dim3 grid(NJB, BSZ / MTILE);  // (48, 2) = 96 CTAs, 1 per SM
    persist_kernel<<<grid, NTHREADS, SMEM_DYN>>>(context, bias_ih, bias_hh, fc_w);

    finalize_kernel<<<BSZ, TSTEPS>>>(num_pred, fc_b, out);
}